// round 1
// baseline (speedup 1.0000x reference)
#include <cuda_runtime.h>

#define BB 32
#define CC 256
#define TT 1024
#define QKVW 384
#define MT (BB*TT)          // 32768 rows

// ---------------- scratch (device globals; no allocations allowed) ----------
__device__ float g_wcat[CC*QKVW];            // [c, n] concat wq|wk|wv
__device__ float g_bcat[QKVW];
__device__ float g_qkv[(size_t)MT*QKVW];     // [b*T+t, 384]  q|k|v
__device__ float g_st[(size_t)BB*TT*TT];     // scores^T then attn^T: [b, j(key), i(query)]
__device__ float g_m[MT];                    // per (b, j) column max
__device__ float g_rz[MT];                   // per (b, j) 1/sumexp
__device__ float g_rowsum[MT];               // sum_k attn[b, q, k]
__device__ float g_wx[MT];                   // weight_x
__device__ float g_h1[(size_t)MT*CC];        // out_attn [b*T+t, c]
__device__ float g_h2[(size_t)MT*CC];        // conv1 out
__device__ float g_w1t[3*CC*CC];             // [(k*256+i), o] normalized
__device__ float g_w2t[3*CC*CC];

// ---------------- prep kernels ----------------------------------------------
__global__ void k_prep_wcat(const float* __restrict__ wq, const float* __restrict__ bq,
                            const float* __restrict__ wk, const float* __restrict__ bk,
                            const float* __restrict__ wv, const float* __restrict__ bv) {
    int idx = blockIdx.x * blockDim.x + threadIdx.x;
    if (idx < CC*QKVW) {
        int c = idx / QKVW, n = idx % QKVW;
        float w;
        if (n < 64)       w = wq[c*64 + n];
        else if (n < 128) w = wk[c*64 + (n-64)];
        else              w = wv[c*256 + (n-128)];
        g_wcat[idx] = w;
    }
    if (idx < QKVW) {
        int n = idx;
        g_bcat[n] = (n < 64) ? bq[n] : (n < 128) ? bk[n-64] : bv[n-128];
    }
}

// weight-norm + transpose conv weights. 512 blocks: layer = bx>>8, o = bx&255.
__global__ void k_prep_convw(const float* __restrict__ v1, const float* __restrict__ g1,
                             const float* __restrict__ v2, const float* __restrict__ g2) {
    int layer = blockIdx.x >> 8;
    int o = blockIdx.x & 255;
    const float* v = layer ? v2 : v1;
    const float* g = layer ? g2 : g1;
    float* wt = layer ? g_w2t : g_w1t;
    int tid = threadIdx.x;   // 256, one per in-channel i
    float vv[3];
    float part = 0.f;
#pragma unroll
    for (int k = 0; k < 3; k++) {
        vv[k] = v[((size_t)o*CC + tid)*3 + k];
        part += vv[k]*vv[k];
    }
    __shared__ float sm[256];
    sm[tid] = part; __syncthreads();
    for (int s = 128; s > 0; s >>= 1) {
        if (tid < s) sm[tid] += sm[tid+s];
        __syncthreads();
    }
    float scale = g[o] * rsqrtf(sm[0]);
#pragma unroll
    for (int k = 0; k < 3; k++)
        wt[(size_t)(k*CC + tid)*CC + o] = scale * vv[k];
}

// ---------------- GEMM 1: qkv = x^T @ wcat + bcat ----------------------------
__global__ void __launch_bounds__(256) k_qkv(const float* __restrict__ x) {
    __shared__ float as[16][64];   // [c_chunk][m]  (x is t-contiguous)
    __shared__ float bs[16][64];   // [c_chunk][n]
    int m0 = blockIdx.x * 64;
    int n0 = blockIdx.y * 64;
    int b = m0 / TT, t0 = m0 % TT;
    int tid = threadIdx.x, tx = tid & 15, ty = tid >> 4;
    float acc[4][4] = {};
    const float* xb = x + (size_t)b*CC*TT;
    for (int kc = 0; kc < CC; kc += 16) {
#pragma unroll
        for (int r = 0; r < 4; r++) {
            int e = tid + 256*r; int mm = e & 63, c = e >> 6;
            as[c][mm] = xb[(size_t)(kc + c)*TT + t0 + mm];
            bs[c][mm] = g_wcat[(size_t)(kc + c)*QKVW + n0 + mm];
        }
        __syncthreads();
#pragma unroll
        for (int d = 0; d < 16; d++) {
            float4 a4 = *(const float4*)&as[d][ty*4];
            float4 b4 = *(const float4*)&bs[d][tx*4];
            float av[4] = {a4.x,a4.y,a4.z,a4.w};
            float bv[4] = {b4.x,b4.y,b4.z,b4.w};
#pragma unroll
            for (int ii = 0; ii < 4; ii++)
#pragma unroll
                for (int jj = 0; jj < 4; jj++)
                    acc[ii][jj] += av[ii]*bv[jj];
        }
        __syncthreads();
    }
#pragma unroll
    for (int ii = 0; ii < 4; ii++) {
        int m = m0 + ty*4 + ii;
#pragma unroll
        for (int jj = 0; jj < 4; jj++) {
            int n = n0 + tx*4 + jj;
            g_qkv[(size_t)m*QKVW + n] = acc[ii][jj] + g_bcat[n];
        }
    }
}

// ---------------- GEMM 2: st[b,j,i] = (k[j] . q[i]) / 8, lower band only -----
__global__ void __launch_bounds__(256) k_scores() {
    int i0 = blockIdx.x * 64, j0 = blockIdx.y * 64, b = blockIdx.z;
    if (j0 > i0) return;                       // fully masked tile
    __shared__ float as[16][68];               // k: [d][j]
    __shared__ float bs[16][68];               // q: [d][i]
    int tid = threadIdx.x, tx = tid & 15, ty = tid >> 4;
    float acc[4][4] = {};
    const float* qb = g_qkv + (size_t)b*TT*QKVW;
    for (int kc = 0; kc < 64; kc += 16) {
#pragma unroll
        for (int r = 0; r < 4; r++) {
            int e = tid + 256*r; int d = e & 15, rr = e >> 4;
            as[d][rr] = qb[(size_t)(j0 + rr)*QKVW + 64 + kc + d];
            bs[d][rr] = qb[(size_t)(i0 + rr)*QKVW +  0 + kc + d];
        }
        __syncthreads();
#pragma unroll
        for (int d = 0; d < 16; d++) {
            float4 a4 = *(const float4*)&as[d][ty*4];
            float4 b4 = *(const float4*)&bs[d][tx*4];
            float av[4] = {a4.x,a4.y,a4.z,a4.w};
            float bv[4] = {b4.x,b4.y,b4.z,b4.w};
#pragma unroll
            for (int ii = 0; ii < 4; ii++)
#pragma unroll
                for (int jj = 0; jj < 4; jj++)
                    acc[ii][jj] += av[ii]*bv[jj];
        }
        __syncthreads();
    }
    size_t base = (size_t)b*TT*TT;
#pragma unroll
    for (int ii = 0; ii < 4; ii++) {
        int j = j0 + ty*4 + ii;
#pragma unroll
        for (int jj = 0; jj < 4; jj++) {
            int i = i0 + tx*4 + jj;
            g_st[base + (size_t)j*TT + i] = acc[ii][jj] * 0.125f;
        }
    }
}

// ---------------- per-(b,j) softmax stats over i in [j, T) -------------------
__global__ void k_stats() {
    int row = blockIdx.x;          // b*T + j
    int b = row >> 10, j = row & 1023;
    const float* p = g_st + (size_t)b*TT*TT + (size_t)j*TT;
    int tid = threadIdx.x;         // 128
    __shared__ float sm[128];
    float mx = -1e30f;
    for (int i = j + tid; i < TT; i += 128) mx = fmaxf(mx, p[i]);
    sm[tid] = mx; __syncthreads();
    for (int s = 64; s > 0; s >>= 1) {
        if (tid < s) sm[tid] = fmaxf(sm[tid], sm[tid+s]);
        __syncthreads();
    }
    mx = sm[0]; __syncthreads();
    float sum = 0.f;
    for (int i = j + tid; i < TT; i += 128) sum += __expf(p[i] - mx);
    sm[tid] = sum; __syncthreads();
    for (int s = 64; s > 0; s >>= 1) {
        if (tid < s) sm[tid] += sm[tid+s];
        __syncthreads();
    }
    if (tid == 0) { g_m[row] = mx; g_rz[row] = 1.f / sm[0]; }
}

// ---------------- attn^T in place (zeros in masked part of band) -------------
__global__ void __launch_bounds__(256) k_attn() {
    int i0 = blockIdx.x * 64, j0 = blockIdx.y * 64, b = blockIdx.z;
    if (j0 > i0) return;
    int tid = threadIdx.x;
    int iof = tid & 63, jr = tid >> 6;         // 4 j-rows per pass
    size_t base = (size_t)b*TT*TT;
#pragma unroll 4
    for (int r = 0; r < 16; r++) {
        int j = j0 + jr*16 + r;
        float mj = g_m[b*TT + j];
        float rz = g_rz[b*TT + j];
        size_t idx = base + (size_t)j*TT + i0 + iof;
        int i = i0 + iof;
        float a = 0.f;
        if (i >= j) a = __expf(g_st[idx] - mj) * rz;
        g_st[idx] = a;
    }
}

// ---------------- rowsum[b,i] = sum_j attn^T[b,j,i]  (deterministic) ---------
__global__ void k_rowsum() {
    int i0 = blockIdx.x * 64, b = blockIdx.y;
    int tid = threadIdx.x;
    int il = tid & 63, jr = tid >> 6;
    const float* ab = g_st + (size_t)b*TT*TT;
    float s = 0.f;
    int jmax = i0 + 64;                        // attn zero beyond the band
    for (int j = jr; j < jmax; j += 4) s += ab[(size_t)j*TT + i0 + il];
    __shared__ float sp[4][64];
    sp[jr][il] = s; __syncthreads();
    if (tid < 64)
        g_rowsum[b*TT + i0 + tid] = sp[0][tid] + sp[1][tid] + sp[2][tid] + sp[3][tid];
}

// ---------------- weight_x = softmax_t(rowsum) -------------------------------
__global__ void k_wx() {
    int b = blockIdx.x, tid = threadIdx.x;     // 256 threads, T=1024
    __shared__ float sm[256];
    float v[4], e[4];
    float mx = -1e30f;
#pragma unroll
    for (int r = 0; r < 4; r++) {
        v[r] = g_rowsum[b*TT + tid + r*256];
        mx = fmaxf(mx, v[r]);
    }
    sm[tid] = mx; __syncthreads();
    for (int s = 128; s > 0; s >>= 1) {
        if (tid < s) sm[tid] = fmaxf(sm[tid], sm[tid+s]);
        __syncthreads();
    }
    mx = sm[0]; __syncthreads();
    float sum = 0.f;
#pragma unroll
    for (int r = 0; r < 4; r++) { e[r] = __expf(v[r] - mx); sum += e[r]; }
    sm[tid] = sum; __syncthreads();
    for (int s = 128; s > 0; s >>= 1) {
        if (tid < s) sm[tid] += sm[tid+s];
        __syncthreads();
    }
    float rz = 1.f / sm[0];
#pragma unroll
    for (int r = 0; r < 4; r++) g_wx[b*TT + tid + r*256] = e[r] * rz;
}

// ---------------- GEMM 3: h1[b,i,c] = sum_j attn^T[b,j,i] * v[b,j,c] ---------
__global__ void __launch_bounds__(256) k_av() {
    int m0 = blockIdx.x * 64, n0 = blockIdx.y * 64;
    int b = m0 / TT, i0 = m0 % TT;
    __shared__ float as[16][64];   // attn^T chunk: [j][i], i contiguous
    __shared__ float bs[16][64];   // v chunk: [j][c]
    int tid = threadIdx.x, tx = tid & 15, ty = tid >> 4;
    float acc[4][4] = {};
    const float* ab = g_st + (size_t)b*TT*TT;
    const float* vb = g_qkv + (size_t)b*TT*QKVW + 128;
    int jmax = i0 + 64;                        // causal band
    for (int j0 = 0; j0 < jmax; j0 += 16) {
#pragma unroll
        for (int r = 0; r < 4; r++) {
            int e = tid + 256*r; int mm = e & 63, c = e >> 6;
            as[c][mm] = ab[(size_t)(j0 + c)*TT + i0 + mm];
            bs[c][mm] = vb[(size_t)(j0 + c)*QKVW + n0 + mm];
        }
        __syncthreads();
#pragma unroll
        for (int d = 0; d < 16; d++) {
            float4 a4 = *(const float4*)&as[d][ty*4];
            float4 b4 = *(const float4*)&bs[d][tx*4];
            float av[4] = {a4.x,a4.y,a4.z,a4.w};
            float bv[4] = {b4.x,b4.y,b4.z,b4.w};
#pragma unroll
            for (int ii = 0; ii < 4; ii++)
#pragma unroll
                for (int jj = 0; jj < 4; jj++)
                    acc[ii][jj] += av[ii]*bv[jj];
        }
        __syncthreads();
    }
#pragma unroll
    for (int ii = 0; ii < 4; ii++) {
        int m = m0 + ty*4 + ii;
#pragma unroll
        for (int jj = 0; jj < 4; jj++)
            g_h1[(size_t)m*CC + n0 + tx*4 + jj] = acc[ii][jj];
    }
}

// ---------------- causal conv as K=768 GEMM; mode1 fuses final epilogue ------
__global__ void __launch_bounds__(256) k_conv(int mode,
                                              const float* __restrict__ bias,
                                              const float* __restrict__ x,
                                              float* __restrict__ outp) {
    const float* h  = (mode == 0) ? g_h1  : g_h2;
    const float* wt = (mode == 0) ? g_w1t : g_w2t;
    int m0 = blockIdx.x * 64, n0 = blockIdx.y * 64;
    int b = m0 / TT, t0 = m0 % TT;
    __shared__ float as[16][68];   // h chunk: [i_sub][t], written i-major (padded)
    __shared__ float bs[16][64];   // wt chunk: [i_sub][o]
    int tid = threadIdx.x, tx = tid & 15, ty = tid >> 4;
    float acc[4][4] = {};
    for (int kc = 0; kc < 48; kc++) {
        int k = kc >> 4, io = (kc & 15) << 4;
#pragma unroll
        for (int r = 0; r < 4; r++) {
            int e = tid + 256*r; int d = e & 15, mm = e >> 4;
            int tt2 = t0 + mm - 2 + k;
            as[d][mm] = (tt2 >= 0) ? h[((size_t)b*TT + tt2)*CC + io + d] : 0.f;
        }
#pragma unroll
        for (int r = 0; r < 4; r++) {
            int e = tid + 256*r; int nn = e & 63, d = e >> 6;
            bs[d][nn] = wt[(size_t)(kc*16 + d)*CC + n0 + nn];
        }
        __syncthreads();
#pragma unroll
        for (int d = 0; d < 16; d++) {
            float4 a4 = *(const float4*)&as[d][ty*4];
            float4 b4 = *(const float4*)&bs[d][tx*4];
            float av[4] = {a4.x,a4.y,a4.z,a4.w};
            float bv[4] = {b4.x,b4.y,b4.z,b4.w};
#pragma unroll
            for (int ii = 0; ii < 4; ii++)
#pragma unroll
                for (int jj = 0; jj < 4; jj++)
                    acc[ii][jj] += av[ii]*bv[jj];
        }
        __syncthreads();
    }
    if (mode == 0) {
#pragma unroll
        for (int ii = 0; ii < 4; ii++) {
            int m = m0 + ty*4 + ii;
#pragma unroll
            for (int jj = 0; jj < 4; jj++) {
                int n = n0 + tx*4 + jj;
                g_h2[(size_t)m*CC + n] = fmaxf(acc[ii][jj] + bias[n], 0.f);
            }
        }
    } else {
#pragma unroll
        for (int ii = 0; ii < 4; ii++) {
            int t = t0 + ty*4 + ii;
            float wxv = g_wx[b*TT + t];
#pragma unroll
            for (int jj = 0; jj < 4; jj++) {
                int n = n0 + tx*4 + jj;
                float cv = fmaxf(acc[ii][jj] + bias[n], 0.f);
                size_t oidx = (size_t)b*CC*TT + (size_t)n*TT + t;
                float xv = x[oidx];
                outp[oidx] = fmaxf(cv + xv * (1.f + wxv), 0.f);
            }
        }
    }
}

// ---------------- launch ------------------------------------------------------
extern "C" void kernel_launch(void* const* d_in, const int* in_sizes, int n_in,
                              void* d_out, int out_size) {
    const float* x  = (const float*)d_in[0];
    const float* wq = (const float*)d_in[1];
    const float* bq = (const float*)d_in[2];
    const float* wk = (const float*)d_in[3];
    const float* bk = (const float*)d_in[4];
    const float* wv = (const float*)d_in[5];
    const float* bv = (const float*)d_in[6];
    const float* v1 = (const float*)d_in[7];
    const float* g1 = (const float*)d_in[8];
    const float* b1 = (const float*)d_in[9];
    const float* v2 = (const float*)d_in[10];
    const float* g2 = (const float*)d_in[11];
    const float* b2 = (const float*)d_in[12];
    float* out = (float*)d_out;

    k_prep_wcat<<<(CC*QKVW + 255)/256, 256>>>(wq, bq, wk, bk, wv, bv);
    k_prep_convw<<<512, 256>>>(v1, g1, v2, g2);
    k_qkv<<<dim3(MT/64, QKVW/64), 256>>>(x);
    k_scores<<<dim3(16, 16, BB), 256>>>();
    k_stats<<<MT, 128>>>();
    k_attn<<<dim3(16, 16, BB), 256>>>();
    k_rowsum<<<dim3(16, BB), 256>>>();
    k_wx<<<BB, 256>>>();
    k_av<<<dim3(MT/64, CC/64), 256>>>();
    k_conv<<<dim3(MT/64, CC/64), 256>>>(0, b1, x, out);
    k_conv<<<dim3(MT/64, CC/64), 256>>>(1, b2, x, out);
}